// round 3
// baseline (speedup 1.0000x reference)
#include <cuda_runtime.h>

// Bidirectional LSTM, H=39, B=512, T=2048, fp32.
// 256 persistent blocks x 160 threads; block = 4 (batch,dir) sequences.
// Lane mapping: tid = jj*4 + gp*2 + kh
//   jj = hidden index (0..38; jj=39 lanes idle-but-participating)
//   gp = gate pair: 0 -> rows (i, f), 1 -> rows (g, o)
//   kh = K half: covers input/hidden elements [20*kh, 20*kh+20)
// Per step: one barrier; gate reduce + exchange via warp shuffles (xor 1, xor 2).
// Weights live in registers (80 regs/thread). x prefetched 2 steps ahead.

#define H        39
#define T_STEPS  2048
#define SPB      4
#define THREADS  160
#define PADW     40     // padded row length (element 39 stays 0)

union F2U { float2 f; unsigned long long u; };

__device__ __forceinline__ float2 ffma2(float2 a, float2 b, float2 c) {
    F2U A, B, C, D;
    A.f = a; B.f = b; C.f = c;
    asm("fma.rn.f32x2 %0, %1, %2, %3;" : "=l"(D.u) : "l"(A.u), "l"(B.u), "l"(C.u));
    return D.f;
}

__device__ __forceinline__ float fast_tanh(float v) {
    float e = __expf(v + v);
    return __fdividef(e - 1.0f, e + 1.0f);
}

struct Smem {
    float sx[2][SPB][PADW];
    float sh[2][SPB][PADW];
};

__global__ __launch_bounds__(THREADS, 2) void lstm_bidir_kernel(
    const float* __restrict__ x,
    const float* __restrict__ Wih_f, const float* __restrict__ Whh_f,
    const float* __restrict__ bih_f, const float* __restrict__ bhh_f,
    const float* __restrict__ Wih_b, const float* __restrict__ Whh_b,
    const float* __restrict__ bih_b, const float* __restrict__ bhh_b,
    float* __restrict__ out)
{
    __shared__ __align__(16) Smem sm;

    const int tid   = threadIdx.x;
    const int bx    = blockIdx.x;
    const int dir   = bx >> 7;
    const int bbase = (bx & 127) * SPB;

    const float* Wih = dir ? Wih_b : Wih_f;
    const float* Whh = dir ? Whh_b : Whh_f;
    const float* bih = dir ? bih_b : bih_f;
    const float* bhh = dir ? bhh_b : bhh_f;

    const int kh = tid & 1;
    const int gp = (tid >> 1) & 1;
    const int jj = tid >> 2;                 // 0..39
    const bool valid = (jj < H);
    const int jc = valid ? jj : (H - 1);     // clamp for safe weight reads

    const int r0 = gp ? (2 * H + jc) : jc;         // row for gate i or g
    const int r1 = gp ? (3 * H + jc) : (H + jc);   // row for gate f or o
    const int kbase = 20 * kh;

    // ---- weights in registers: 2 rows x half-K, ih + hh -> 40 f32x2 ----
    float2 wi0[10], wh0[10], wi1[10], wh1[10];
    #pragma unroll
    for (int k = 0; k < 10; k++) {
        const int i0 = kbase + 2 * k;
        const int i1 = i0 + 1;
        const float e0a = Wih[r0 * H + i0];
        const float e0b = (i1 < H) ? Wih[r0 * H + i1] : 0.0f;
        const float e1a = Wih[r1 * H + i0];
        const float e1b = (i1 < H) ? Wih[r1 * H + i1] : 0.0f;
        const float h0a = Whh[r0 * H + i0];
        const float h0b = (i1 < H) ? Whh[r0 * H + i1] : 0.0f;
        const float h1a = Whh[r1 * H + i0];
        const float h1b = (i1 < H) ? Whh[r1 * H + i1] : 0.0f;
        wi0[k] = make_float2(e0a, e0b);
        wi1[k] = make_float2(e1a, e1b);
        wh0[k] = make_float2(h0a, h0b);
        wh1[k] = make_float2(h1a, h1b);
    }
    const float bias0 = bih[r0] + bhh[r0];
    const float bias1 = bih[r1] + bhh[r1];
    const float is_g  = gp ? 1.0f : 0.0f;    // row0 is tanh gate when gp==1

    // ---- loader role: seq ls, element lj ----
    const int  ls = tid / 40;
    const int  lj = tid - 40 * ls;
    const bool lactive = (lj < H);

    const int xstep = dir ? -H : H;
    const float* xptr = x + (size_t)(bbase + ls) * (T_STEPS * H)
                          + (dir ? (T_STEPS - 1) * H : 0) + lj;

    // ---- zero smem (incl. pad element 39, both buffers) ----
    float* smf = &sm.sx[0][0][0];
    for (int idx = tid; idx < 4 * SPB * PADW; idx += THREADS) smf[idx] = 0.0f;

    float xn0 = 0.0f, xn1 = 0.0f;
    if (lactive) {
        xn0 = __ldg(xptr);
        xn1 = __ldg(xptr + xstep);
    }
    const float* xq = xptr + 2 * xstep;

    // store x_0
    if (lactive) sm.sx[0][ls][lj] = xn0;

    // writer roles
    const bool wrh = (kh == 0) && (gp == 0) && valid;   // writes sh
    const bool wro = (kh == 1) && (gp == 0) && valid;   // writes out

    float c[SPB] = {0.f, 0.f, 0.f, 0.f};

    const size_t oseq = (size_t)T_STEPS * 2 * H;
    float* obase = out + (size_t)bbase * oseq + dir * H + jj;

    __syncthreads();

    #pragma unroll 2
    for (int t = 0; t < T_STEPS; t++) {
        const int cur = t & 1;
        const int nxt = cur ^ 1;

        // loader: publish x_{t+1}, prefetch x_{t+2}
        if (lactive && (t + 1 < T_STEPS)) sm.sx[nxt][ls][lj] = xn1;
        float xload = 0.0f;
        if (lactive && (t + 2 < T_STEPS)) xload = __ldg(xq);
        xq += xstep;
        xn1 = xload;

        #pragma unroll
        for (int ss = 0; ss < SPB; ss++) {
            const float4* xv4 = reinterpret_cast<const float4*>(&sm.sx[cur][ss][kbase]);
            const float4* hv4 = reinterpret_cast<const float4*>(&sm.sh[cur][ss][kbase]);

            float2 aI0 = make_float2(0.f, 0.f), aH0 = make_float2(0.f, 0.f);
            float2 aI1 = make_float2(0.f, 0.f), aH1 = make_float2(0.f, 0.f);
            #pragma unroll
            for (int k = 0; k < 5; k++) {
                const float4 xv = xv4[k];
                const float4 hv = hv4[k];
                const float2 xlo = make_float2(xv.x, xv.y);
                const float2 xhi = make_float2(xv.z, xv.w);
                const float2 hlo = make_float2(hv.x, hv.y);
                const float2 hhi = make_float2(hv.z, hv.w);
                aI0 = ffma2(wi0[2 * k],     xlo, aI0);
                aI0 = ffma2(wi0[2 * k + 1], xhi, aI0);
                aH0 = ffma2(wh0[2 * k],     hlo, aH0);
                aH0 = ffma2(wh0[2 * k + 1], hhi, aH0);
                aI1 = ffma2(wi1[2 * k],     xlo, aI1);
                aI1 = ffma2(wi1[2 * k + 1], xhi, aI1);
                aH1 = ffma2(wh1[2 * k],     hlo, aH1);
                aH1 = ffma2(wh1[2 * k + 1], hhi, aH1);
            }
            float p0 = (aI0.x + aI0.y) + (aH0.x + aH0.y);
            float p1 = (aI1.x + aI1.y) + (aH1.x + aH1.y);

            // k-half reduction (xor 1): both halves end with the same totals
            p0 += __shfl_xor_sync(0xffffffffu, p0, 1);
            p1 += __shfl_xor_sync(0xffffffffu, p1, 1);
            p0 += bias0;
            p1 += bias1;

            // row0: sigmoid (i) if gp==0, tanh (g) if gp==1. row1: always sigmoid.
            const float arg0 = gp ? (p0 + p0) : (-p0);
            const float e0   = __expf(arg0);
            const float num0 = gp ? (e0 - 1.0f) : 1.0f;
            const float g0   = __fdividef(num0, e0 + 1.0f);
            const float e1   = __expf(-p1);
            const float g1   = __fdividef(1.0f, e1 + 1.0f);

            // gate-pair exchange (xor 2)
            const float q0 = __shfl_xor_sync(0xffffffffu, g0, 2);
            const float q1 = __shfl_xor_sync(0xffffffffu, g1, 2);

            const float gi = gp ? q0 : g0;
            const float gf = gp ? q1 : g1;
            const float gg = gp ? g0 : q0;
            const float go = gp ? g1 : q1;

            const float cn = gf * c[ss] + gi * gg;
            c[ss] = cn;
            const float h = go * fast_tanh(cn);

            if (wrh) sm.sh[nxt][ss][jj] = h;
            if (wro) obase[(size_t)ss * oseq + (size_t)t * (2 * H)] = h;
        }

        __syncthreads();
    }
    (void)is_g;
}

extern "C" void kernel_launch(void* const* d_in, const int* in_sizes, int n_in,
                              void* d_out, int out_size) {
    const float* x     = (const float*)d_in[0];
    const float* Wih_f = (const float*)d_in[1];
    const float* Whh_f = (const float*)d_in[2];
    const float* bih_f = (const float*)d_in[3];
    const float* bhh_f = (const float*)d_in[4];
    const float* Wih_b = (const float*)d_in[5];
    const float* Whh_b = (const float*)d_in[6];
    const float* bih_b = (const float*)d_in[7];
    const float* bhh_b = (const float*)d_in[8];
    float* out = (float*)d_out;

    lstm_bidir_kernel<<<256, THREADS>>>(x, Wih_f, Whh_f, bih_f, bhh_f,
                                        Wih_b, Whh_b, bih_b, bhh_b, out);
}

// round 7
// speedup vs baseline: 1.2377x; 1.2377x over previous
#include <cuda_runtime.h>

// Bidirectional LSTM, H=39, B=512, T=2048, fp32.
// 256 persistent blocks x 160 threads (5 warps), 2 blocks/SM; block = 4 seqs.
// Lane map: tid = 4*j + g  (g = gate 0..3 [i,f,g,o], j = hidden idx 0..39; j=39 idle).
// Thread owns full gate row (W_ih + W_hh rows, 80 regs), computes it for 4 seqs.
// The 4 gates of (j, all 4 seqs) live in 4 adjacent lanes -> a 4-shuffle 4x4
// lane transpose hands lane g all four activated gates of SEQ g. Each thread
// then owns exactly one (seq, j) cell state: no redundant tanh, no 2nd barrier.
// sx/sh are ping-pong buffered -> single __syncthreads per step.

#define H        39
#define T_STEPS  2048
#define SPB      4
#define THREADS  160
#define PADW     40

union F2U { float2 f; unsigned long long u; };

__device__ __forceinline__ float2 ffma2(float2 a, float2 b, float2 c) {
    F2U A, B, C, D;
    A.f = a; B.f = b; C.f = c;
    asm("fma.rn.f32x2 %0, %1, %2, %3;" : "=l"(D.u) : "l"(A.u), "l"(B.u), "l"(C.u));
    return D.f;
}

struct Smem {
    float sx[2][SPB][PADW];
    float sh[2][SPB][PADW];
};

__global__ __launch_bounds__(THREADS, 2) void lstm_bidir_kernel(
    const float* __restrict__ x,
    const float* __restrict__ Wih_f, const float* __restrict__ Whh_f,
    const float* __restrict__ bih_f, const float* __restrict__ bhh_f,
    const float* __restrict__ Wih_b, const float* __restrict__ Whh_b,
    const float* __restrict__ bih_b, const float* __restrict__ bhh_b,
    float* __restrict__ out)
{
    __shared__ __align__(16) Smem sm;

    const int tid   = threadIdx.x;
    const int bx    = blockIdx.x;
    const int dir   = bx >> 7;
    const int bbase = (bx & 127) * SPB;

    const float* Wih = dir ? Wih_b : Wih_f;
    const float* Whh = dir ? Whh_b : Whh_f;
    const float* bih = dir ? bih_b : bih_f;
    const float* bhh = dir ? bhh_b : bhh_f;

    const int g  = tid & 3;          // gate: 0=i 1=f 2=g 3=o
    const int jj = tid >> 2;         // hidden index 0..39
    const bool valid = (jj < H);
    const int jc = valid ? jj : (H - 1);
    const int row = g * H + jc;      // gate row in [0,156)

    // ---- full gate row in registers: 20+20 float2 = 80 regs ----
    float2 wih2[20], whh2[20];
    #pragma unroll
    for (int k = 0; k < 20; k++) {
        const int i0 = 2 * k, i1 = 2 * k + 1;
        const float a0 = Wih[row * H + i0];
        const float a1 = (i1 < H) ? Wih[row * H + i1] : 0.0f;
        const float b0 = Whh[row * H + i0];
        const float b1 = (i1 < H) ? Whh[row * H + i1] : 0.0f;
        wih2[k] = make_float2(a0, a1);
        whh2[k] = make_float2(b0, b1);
    }
    const float bias = bih[row] + bhh[row];

    // activation constants per gate type (g==2 -> tanh, else sigmoid)
    const float mconst = (g == 2) ?  2.0f : -1.0f;   // exp argument scale
    const float nA     = (g == 2) ?  1.0f :  0.0f;   // numerator = fma(e,nA,nB)
    const float nB     = (g == 2) ? -1.0f :  1.0f;

    // ---- loader role: seq ls, element lj ----
    const int  ls = tid / 40;
    const int  lj = tid - 40 * ls;
    const bool lactive = (lj < H);

    const int xstep = dir ? -H : H;
    const float* xptr = x + (size_t)(bbase + ls) * (T_STEPS * H)
                          + (dir ? (T_STEPS - 1) * H : 0) + lj;

    // ---- zero smem (both buffers incl. pads) ----
    float* smf = &sm.sx[0][0][0];
    for (int idx = tid; idx < 4 * SPB * PADW; idx += THREADS) smf[idx] = 0.0f;

    // 2-deep x prefetch: xA = x_{t+1}, xB = x_{t+2}
    float x0 = 0.f, xA = 0.f, xB = 0.f;
    if (lactive) {
        x0 = __ldg(xptr);
        xA = __ldg(xptr + xstep);
        xB = __ldg(xptr + 2 * xstep);
    }
    const float* xq = xptr + 3 * xstep;
    if (lactive) sm.sx[0][ls][lj] = x0;

    // this thread's cell state: seq index == g
    float c = 0.0f;
    const size_t oseq = (size_t)T_STEPS * 2 * H;
    float* op = out + (size_t)(bbase + g) * oseq + dir * H + jj;

    __syncthreads();

    #pragma unroll 1
    for (int t = 0; t < T_STEPS; t++) {
        const int cur = t & 1;
        const int nxt = cur ^ 1;

        // publish x_{t+1}; refill prefetch pipe with x_{t+3}
        if (lactive && (t + 1 < T_STEPS)) sm.sx[nxt][ls][lj] = xA;
        float xload = 0.0f;
        if (lactive && (t + 3 < T_STEPS)) xload = __ldg(xq);
        xq += xstep;
        xA = xB; xB = xload;

        // ---- gate value of THIS row for each of the 4 seqs ----
        float a[SPB];
        #pragma unroll
        for (int ss = 0; ss < SPB; ss++) {
            const float4* x4 = reinterpret_cast<const float4*>(sm.sx[cur][ss]);
            const float4* h4 = reinterpret_cast<const float4*>(sm.sh[cur][ss]);
            float2 aI = make_float2(0.f, 0.f);
            float2 aH = make_float2(0.f, 0.f);
            #pragma unroll
            for (int k = 0; k < 10; k++) {
                const float4 xv = x4[k];
                const float4 hv = h4[k];
                aI = ffma2(wih2[2 * k],     make_float2(xv.x, xv.y), aI);
                aI = ffma2(wih2[2 * k + 1], make_float2(xv.z, xv.w), aI);
                aH = ffma2(whh2[2 * k],     make_float2(hv.x, hv.y), aH);
                aH = ffma2(whh2[2 * k + 1], make_float2(hv.z, hv.w), aH);
            }
            const float p = bias + (aI.x + aI.y) + (aH.x + aH.y);
            // sigmoid(p) = 1/(1+e^-p)      (mconst=-1, num=1)
            // tanh(p)    = (e^2p-1)/(e^2p+1) (mconst=+2, num=e-1)
            const float e = __expf(p * mconst);
            a[ss] = __fdividef(fmaf(e, nA, nB), e + 1.0f);
        }

        // ---- 4x4 lane transpose: lane g ends with gates [i,f,g,o] of seq g ----
        const unsigned M = 0xffffffffu;
        const bool o1 = (g & 1);
        const float rA = __shfl_xor_sync(M, o1 ? a[0] : a[1], 1);
        const float rB = __shfl_xor_sync(M, o1 ? a[2] : a[3], 1);
        const float n10 = o1 ? rA  : a[0];
        const float n11 = o1 ? a[1] : rA;
        const float n12 = o1 ? rB  : a[2];
        const float n13 = o1 ? a[3] : rB;
        const bool o2 = (g & 2);
        const float rC = __shfl_xor_sync(M, o2 ? n10 : n12, 2);
        const float rD = __shfl_xor_sync(M, o2 ? n11 : n13, 2);
        const float gi = o2 ? rC  : n10;
        const float gf = o2 ? rD  : n11;
        const float gg = o2 ? n12 : rC;
        const float go = o2 ? n13 : rD;

        // ---- this thread's (seq=g, j) cell update ----
        c = gf * c + gi * gg;
        const float e2 = __expf(c + c);
        const float th = 1.0f - 2.0f * __fdividef(1.0f, e2 + 1.0f); // tanh(c)
        const float h  = go * th;

        if (valid) {
            sm.sh[nxt][g][jj] = h;
            op[(size_t)t * (2 * H)] = h;
        }

        __syncthreads();
    }
}

extern "C" void kernel_launch(void* const* d_in, const int* in_sizes, int n_in,
                              void* d_out, int out_size) {
    const float* x     = (const float*)d_in[0];
    const float* Wih_f = (const float*)d_in[1];
    const float* Whh_f = (const float*)d_in[2];
    const float* bih_f = (const float*)d_in[3];
    const float* bhh_f = (const float*)d_in[4];
    const float* Wih_b = (const float*)d_in[5];
    const float* Whh_b = (const float*)d_in[6];
    const float* bih_b = (const float*)d_in[7];
    const float* bhh_b = (const float*)d_in[8];
    float* out = (float*)d_out;

    lstm_bidir_kernel<<<256, THREADS>>>(x, Wih_f, Whh_f, bih_f, bhh_f,
                                        Wih_b, Whh_b, bih_b, bhh_b, out);
}

// round 8
// speedup vs baseline: 1.3344x; 1.0781x over previous
#include <cuda_runtime.h>

// Bidirectional LSTM, H=39, B=512, T=2048, fp32.
// 444 persistent blocks x 160 threads, exactly 3 blocks resident per SM
// (444 = 148*3). Blocks 0..135 own 3 sequences, blocks 136..443 own 2
// (136*3 + 308*2 = 1024). Block ids 0..135 are distinct mod 148 -> each SM
// hosts at most one 3-seq block -> max 7 seqs/SM, perfectly balanced.
// Lane map: tid = 4*j + g (g = gate 0..3 [i,f,g,o], j = hidden 0..39).
// Thread holds one full gate row (80 weight regs), computes it for nsq seqs;
// a 4-shuffle 4x4 lane transpose hands lane g all four gates of seq g, which
// that lane's thread owns (c/h update, no redundant tanh). One barrier/step,
// ping-pong sx/sh buffers, f32x2 FMAs, 2-deep x prefetch.

#define H        39
#define T_STEPS  2048
#define MAXS     3
#define THREADS  160
#define PADW     40

union F2U { float2 f; unsigned long long u; };

__device__ __forceinline__ float2 ffma2(float2 a, float2 b, float2 c) {
    F2U A, B, C, D;
    A.f = a; B.f = b; C.f = c;
    asm("fma.rn.f32x2 %0, %1, %2, %3;" : "=l"(D.u) : "l"(A.u), "l"(B.u), "l"(C.u));
    return D.f;
}

struct Smem {
    float sx[2][MAXS][PADW];
    float sh[2][MAXS][PADW];
};

__global__ __launch_bounds__(THREADS, 3) void lstm_bidir_kernel(
    const float* __restrict__ x,
    const float* __restrict__ Wih_f, const float* __restrict__ Whh_f,
    const float* __restrict__ bih_f, const float* __restrict__ bhh_f,
    const float* __restrict__ Wih_b, const float* __restrict__ Whh_b,
    const float* __restrict__ bih_b, const float* __restrict__ bhh_b,
    float* __restrict__ out)
{
    __shared__ __align__(16) Smem sm;

    const int tid = threadIdx.x;
    const int bx  = blockIdx.x;

    // ---- sequence range for this block (never straddles direction split) ----
    int nsq, start;
    if (bx < 136) { nsq = 3; start = 3 * bx; }
    else          { nsq = 2; start = 408 + 2 * (bx - 136); }
    const int dir   = (start >= 512) ? 1 : 0;
    const int bbase = start - dir * 512;          // batch index of first seq

    const float* Wih = dir ? Wih_b : Wih_f;
    const float* Whh = dir ? Whh_b : Whh_f;
    const float* bih = dir ? bih_b : bih_f;
    const float* bhh = dir ? bhh_b : bhh_f;

    const int g  = tid & 3;            // gate 0=i 1=f 2=g 3=o; also "my" seq
    const int jj = tid >> 2;           // hidden index 0..39
    const bool jvalid = (jj < H);
    const int jc  = jvalid ? jj : (H - 1);
    const int row = g * H + jc;

    // ---- full gate row in registers: 20+20 float2 = 80 regs ----
    float2 wih2[20], whh2[20];
    #pragma unroll
    for (int k = 0; k < 20; k++) {
        const int i0 = 2 * k, i1 = 2 * k + 1;
        const float a0 = Wih[row * H + i0];
        const float a1 = (i1 < H) ? Wih[row * H + i1] : 0.0f;
        const float b0 = Whh[row * H + i0];
        const float b1 = (i1 < H) ? Whh[row * H + i1] : 0.0f;
        wih2[k] = make_float2(a0, a1);
        whh2[k] = make_float2(b0, b1);
    }
    const float bias = bih[row] + bhh[row];

    // activation constants (g==2 -> tanh, else sigmoid)
    const float mconst = (g == 2) ?  2.0f : -1.0f;
    const float nA     = (g == 2) ?  1.0f :  0.0f;
    const float nB     = (g == 2) ? -1.0f :  1.0f;

    // ---- loader role: seq ls, element lj ----
    const int  ls = tid / 40;
    const int  lj = tid - 40 * ls;
    const bool lactive = (ls < nsq) && (lj < H);

    const int xstep = dir ? -H : H;
    const float* xptr = x + (size_t)(bbase + (ls < nsq ? ls : 0)) * (T_STEPS * H)
                          + (dir ? (T_STEPS - 1) * H : 0) + lj;

    // ---- zero smem (both buffers incl. pads) ----
    float* smf = &sm.sx[0][0][0];
    for (int idx = tid; idx < 4 * MAXS * PADW; idx += THREADS) smf[idx] = 0.0f;

    // 2-deep x prefetch
    float x0 = 0.f, xA = 0.f, xB = 0.f;
    if (lactive) {
        x0 = __ldg(xptr);
        xA = __ldg(xptr + xstep);
        xB = __ldg(xptr + 2 * xstep);
    }
    const float* xq = xptr + 3 * xstep;
    if (lactive) sm.sx[0][ls][lj] = x0;

    // this thread's cell state: seq index == g (valid when g < nsq)
    const bool owner = (g < nsq) && jvalid;
    float c = 0.0f;
    const size_t oseq = (size_t)T_STEPS * 2 * H;
    float* op = out + (size_t)(bbase + (g < nsq ? g : 0)) * oseq + dir * H + jj;

    __syncthreads();

    #pragma unroll 1
    for (int t = 0; t < T_STEPS; t++) {
        const int cur = t & 1;
        const int nxt = cur ^ 1;

        // publish x_{t+1}; refill pipe with x_{t+3}
        if (lactive && (t + 1 < T_STEPS)) sm.sx[nxt][ls][lj] = xA;
        float xload = 0.0f;
        if (lactive && (t + 3 < T_STEPS)) xload = __ldg(xq);
        xq += xstep;
        xA = xB; xB = xload;

        // ---- this gate row's value for each active seq ----
        float a[MAXS + 1];
        a[0] = a[1] = a[2] = a[3] = 0.0f;
        #pragma unroll
        for (int ss = 0; ss < MAXS; ss++) {
            if (ss < nsq) {
                const float4* x4 = reinterpret_cast<const float4*>(sm.sx[cur][ss]);
                const float4* h4 = reinterpret_cast<const float4*>(sm.sh[cur][ss]);
                float2 aI = make_float2(0.f, 0.f);
                float2 aH = make_float2(0.f, 0.f);
                #pragma unroll
                for (int k = 0; k < 10; k++) {
                    const float4 xv = x4[k];
                    const float4 hv = h4[k];
                    aI = ffma2(wih2[2 * k],     make_float2(xv.x, xv.y), aI);
                    aI = ffma2(wih2[2 * k + 1], make_float2(xv.z, xv.w), aI);
                    aH = ffma2(whh2[2 * k],     make_float2(hv.x, hv.y), aH);
                    aH = ffma2(whh2[2 * k + 1], make_float2(hv.z, hv.w), aH);
                }
                const float p = bias + (aI.x + aI.y) + (aH.x + aH.y);
                // sigmoid(p)=1/(1+e^-p); tanh(p)=(e^{2p}-1)/(e^{2p}+1)
                const float e = __expf(p * mconst);
                a[ss] = __fdividef(fmaf(e, nA, nB), e + 1.0f);
            }
        }

        // ---- 4x4 lane transpose: lane g ends with gates [i,f,g,o] of seq g ----
        const unsigned M = 0xffffffffu;
        const bool o1 = (g & 1);
        const float rA = __shfl_xor_sync(M, o1 ? a[0] : a[1], 1);
        const float rB = __shfl_xor_sync(M, o1 ? a[2] : a[3], 1);
        const float n10 = o1 ? rA   : a[0];
        const float n11 = o1 ? a[1] : rA;
        const float n12 = o1 ? rB   : a[2];
        const float n13 = o1 ? a[3] : rB;
        const bool o2 = (g & 2);
        const float rC = __shfl_xor_sync(M, o2 ? n10 : n12, 2);
        const float rD = __shfl_xor_sync(M, o2 ? n11 : n13, 2);
        const float gi = o2 ? rC  : n10;
        const float gf = o2 ? rD  : n11;
        const float gg = o2 ? n12 : rC;
        const float go = o2 ? n13 : rD;

        // ---- cell update for owned (seq=g, j) ----
        c = gf * c + gi * gg;
        const float e2 = __expf(c + c);
        const float th = 1.0f - 2.0f * __fdividef(1.0f, e2 + 1.0f);  // tanh(c)
        const float h  = go * th;

        if (owner) {
            sm.sh[nxt][g][jj] = h;
            op[(size_t)t * (2 * H)] = h;
        }

        __syncthreads();
    }
}

extern "C" void kernel_launch(void* const* d_in, const int* in_sizes, int n_in,
                              void* d_out, int out_size) {
    const float* x     = (const float*)d_in[0];
    const float* Wih_f = (const float*)d_in[1];
    const float* Whh_f = (const float*)d_in[2];
    const float* bih_f = (const float*)d_in[3];
    const float* bhh_f = (const float*)d_in[4];
    const float* Wih_b = (const float*)d_in[5];
    const float* Whh_b = (const float*)d_in[6];
    const float* bih_b = (const float*)d_in[7];
    const float* bhh_b = (const float*)d_in[8];
    float* out = (float*)d_out;

    lstm_bidir_kernel<<<444, THREADS>>>(x, Wih_f, Whh_f, bih_f, bhh_f,
                                        Wih_b, Whh_b, bih_b, bhh_b, out);
}